// round 15
// baseline (speedup 1.0000x reference)
#include <cuda_runtime.h>
#include <cuda_fp16.h>
#include <cstdint>

#define NTOK 16384

// Scratch (allocation-free rule: __device__ globals)
__device__ __half g_xph[33554432];  // x @ W_in, fp16
__device__ __half g_yh[33554432];   // attention output, fp16
__device__ __half g_wt1[65536];     // W_in^T  [n][k], fp16
__device__ __half g_wt2[65536];     // W_out^T [n][k], fp16

// ---------------------------------------------------------------------------
__device__ __forceinline__ uint32_t smem_u32(const void* p) {
    uint32_t a;
    asm("{ .reg .u64 t; cvta.to.shared.u64 t, %1; cvt.u32.u64 %0, t; }"
        : "=r"(a) : "l"(p));
    return a;
}
__device__ __forceinline__ void mma_fp16(float* d, const uint32_t* a,
                                         const uint32_t* b) {
    asm volatile(
        "mma.sync.aligned.m16n8k16.row.col.f32.f16.f16.f32 "
        "{%0,%1,%2,%3}, {%4,%5,%6,%7}, {%8,%9}, {%0,%1,%2,%3};"
        : "+f"(d[0]), "+f"(d[1]), "+f"(d[2]), "+f"(d[3])
        : "r"(a[0]), "r"(a[1]), "r"(a[2]), "r"(a[3]), "r"(b[0]), "r"(b[1]));
}
#define LDSM4(R0, R1, R2, R3, addr) \
    asm volatile("ldmatrix.sync.aligned.m8n8.x4.shared.b16 {%0,%1,%2,%3}, [%4];" \
                 : "=r"(R0), "=r"(R1), "=r"(R2), "=r"(R3) : "r"(addr))
#define CP_ASYNC16(dst, src) \
    asm volatile("cp.async.ca.shared.global [%0], [%1], 16;" \
                 :: "r"(dst), "l"(src))
#define CP_COMMIT() asm volatile("cp.async.commit_group;")
#define CP_WAIT0()  asm volatile("cp.async.wait_group 0;")

// ---------------------------------------------------------------------------
// Merged transpose + fp16 convert for both weight matrices.
// ---------------------------------------------------------------------------
__global__ void transpose_both(const float* __restrict__ W1,
                               __half* __restrict__ T1,
                               const float* __restrict__ W2,
                               __half* __restrict__ T2)
{
    __shared__ float tile[32][33];
    const int sel = blockIdx.x >> 6;
    const int bb  = blockIdx.x & 63;
    const float* W = sel ? W2 : W1;
    __half*      T = sel ? T2 : T1;
    const int bx = (bb & 7) << 5;
    const int by = (bb >> 3) << 5;
    const int tx = threadIdx.x & 31;
    const int ty = threadIdx.x >> 5;
#pragma unroll
    for (int i = 0; i < 32; i += 8)
        tile[ty + i][tx] = W[(by + ty + i) * 256 + bx + tx];
    __syncthreads();
#pragma unroll
    for (int i = 0; i < 32; i += 8)
        T[(bx + ty + i) * 256 + by + tx] = __float2half_rn(tile[tx][ty + i]);
}

// ---------------------------------------------------------------------------
// GEMM common geometry: CTA 128x128, BK=32, 256 thr, 8 warps (2M x 4N)
// Inner loop restructured for low register pressure: bf loaded once per ks,
// ah loaded per-mf and consumed immediately -> fits 3 CTAs/SM (85 regs).
// ---------------------------------------------------------------------------
#define SROW 80                    // bytes per smem row (32 fp16 + 8 pad)
#define OFF_A 0
#define OFF_B 10240
#define BUFB  20480
#define GEMM_SMEM (2 * BUFB)       // 40960

// === Variant 1: A fp32 in (reg path + cvt), B fp16 cp.async, C fp16 out ====
__global__ __launch_bounds__(256, 3) void gemm_f32in_f16out(
    const float* __restrict__ A, const __half* __restrict__ Bt,
    const float* __restrict__ bias, __half* __restrict__ C)
{
    extern __shared__ char sm[];
    const uint32_t smb = smem_u32(sm);
    const int t    = threadIdx.x;
    const int lane = t & 31;
    const int warp = t >> 5;
    const int wm0  = (warp >> 2) * 64;
    const int wn0  = (warp & 3) * 32;
    const int row0 = blockIdx.y << 7;
    const int col0 = blockIdx.x << 7;

    const int lr = t >> 3;
    const int lk = (t & 7) << 2;
    const int cr = t >> 2;
    const int cs = t & 3;

    float acc[4][4][4];
#pragma unroll
    for (int i = 0; i < 4; i++)
#pragma unroll
        for (int j = 0; j < 4; j++)
#pragma unroll
            for (int k = 0; k < 4; k++) acc[i][j][k] = 0.f;

    float4 pa[4];

    const uint32_t aoff = (uint32_t)(wm0 + (lane & 15)) * SROW + ((lane >> 4) << 4);
    const uint32_t boff = (uint32_t)(wn0 + (lane & 15)) * SROW + ((lane >> 4) << 4);

#define B_ASYNC1(k0, bufoff)                                                    \
    do {                                                                        \
        _Pragma("unroll")                                                       \
        for (int i = 0; i < 2; i++) {                                           \
            const int r = i * 64 + cr;                                          \
            CP_ASYNC16(smb + (bufoff) + OFF_B + (uint32_t)r * SROW + cs * 16,   \
                       Bt + (size_t)(col0 + r) * 256 + (k0) + cs * 8);          \
        }                                                                       \
        CP_COMMIT();                                                            \
    } while (0)

#define A_LOAD1(k0)                                                             \
    do {                                                                        \
        _Pragma("unroll")                                                       \
        for (int i = 0; i < 4; i++)                                             \
            pa[i] = *(const float4*)(A + (size_t)(row0 + i * 32 + lr) * 256 +   \
                                     (k0) + lk);                                \
    } while (0)

#define A_STORE1(bufoff)                                                        \
    do {                                                                        \
        char* base = sm + (bufoff);                                             \
        _Pragma("unroll")                                                       \
        for (int i = 0; i < 4; i++) {                                           \
            const int r = i * 32 + lr;                                          \
            const uint32_t off = (uint32_t)r * SROW + ((t & 7) << 3);           \
            uint2 hh;                                                           \
            __half2 h0 = __floats2half2_rn(pa[i].x, pa[i].y);                   \
            __half2 h1 = __floats2half2_rn(pa[i].z, pa[i].w);                   \
            hh.x = *(uint32_t*)&h0;                                             \
            hh.y = *(uint32_t*)&h1;                                             \
            *(uint2*)(base + OFF_A + off) = hh;                                 \
        }                                                                       \
    } while (0)

    A_LOAD1(0);
    B_ASYNC1(0, 0);
    A_STORE1(0);
    CP_WAIT0();
    __syncthreads();

    for (int c = 0; c < 8; c++) {
        const uint32_t cur = (uint32_t)(c & 1) * BUFB;
        const uint32_t nxt = BUFB - cur;
        if (c < 7) {
            B_ASYNC1((c + 1) * 32, nxt);
            A_LOAD1((c + 1) * 32);
        }

        const uint32_t AB = smb + cur + OFF_A;
        const uint32_t BB = smb + cur + OFF_B;

#pragma unroll
        for (int ks = 0; ks < 2; ks++) {
            const uint32_t kb = ks * 32;
            uint32_t bf[4][2];
#pragma unroll
            for (int np = 0; np < 2; np++) {
                uint32_t r0, r1, r2, r3;
                LDSM4(r0, r1, r2, r3, BB + boff + np * (16 * SROW) + kb);
                bf[2 * np][0] = r0; bf[2 * np][1] = r2;
                bf[2 * np + 1][0] = r1; bf[2 * np + 1][1] = r3;
            }
#pragma unroll
            for (int mf = 0; mf < 4; mf++) {
                uint32_t ah[4];
                LDSM4(ah[0], ah[1], ah[2], ah[3],
                      AB + aoff + mf * (16 * SROW) + kb);
#pragma unroll
                for (int nf = 0; nf < 4; nf++)
                    mma_fp16(acc[mf][nf], ah, bf[nf]);
            }
        }

        if (c < 7) {
            A_STORE1(nxt);
            CP_WAIT0();
        }
        __syncthreads();
    }

#pragma unroll
    for (int nf = 0; nf < 4; nf++) {
        const int cc = col0 + wn0 + nf * 8 + (lane & 3) * 2;
        const float b0 = bias[cc], b1 = bias[cc + 1];
#pragma unroll
        for (int mf = 0; mf < 4; mf++) {
            const int r = row0 + wm0 + mf * 16 + (lane >> 2);
            __half2 o0 = __floats2half2_rn(acc[mf][nf][0] + b0, acc[mf][nf][1] + b1);
            __half2 o1 = __floats2half2_rn(acc[mf][nf][2] + b0, acc[mf][nf][3] + b1);
            *(uint32_t*)(C + (size_t)r * 256 + cc) = *(uint32_t*)&o0;
            *(uint32_t*)(C + (size_t)(r + 8) * 256 + cc) = *(uint32_t*)&o1;
        }
    }
}

// === Variant 2: A fp16 in (cp.async both operands), C fp32 out =============
__global__ __launch_bounds__(256, 3) void gemm_f16in_f32out(
    const __half* __restrict__ A, const __half* __restrict__ Bt,
    const float* __restrict__ bias, float* __restrict__ C)
{
    extern __shared__ char sm[];
    const uint32_t smb = smem_u32(sm);
    const int t    = threadIdx.x;
    const int lane = t & 31;
    const int warp = t >> 5;
    const int wm0  = (warp >> 2) * 64;
    const int wn0  = (warp & 3) * 32;
    const int row0 = blockIdx.y << 7;
    const int col0 = blockIdx.x << 7;

    const int cr = t >> 2;
    const int cs = t & 3;

    float acc[4][4][4];
#pragma unroll
    for (int i = 0; i < 4; i++)
#pragma unroll
        for (int j = 0; j < 4; j++)
#pragma unroll
            for (int k = 0; k < 4; k++) acc[i][j][k] = 0.f;

    const uint32_t aoff = (uint32_t)(wm0 + (lane & 15)) * SROW + ((lane >> 4) << 4);
    const uint32_t boff = (uint32_t)(wn0 + (lane & 15)) * SROW + ((lane >> 4) << 4);

#define ASYNC_CHUNK2(k0, bufoff)                                                \
    do {                                                                        \
        _Pragma("unroll")                                                       \
        for (int i = 0; i < 2; i++) {                                           \
            const int r = i * 64 + cr;                                          \
            const uint32_t off = (uint32_t)r * SROW + cs * 16;                  \
            CP_ASYNC16(smb + (bufoff) + OFF_A + off,                            \
                       A + (size_t)(row0 + r) * 256 + (k0) + cs * 8);           \
            CP_ASYNC16(smb + (bufoff) + OFF_B + off,                            \
                       Bt + (size_t)(col0 + r) * 256 + (k0) + cs * 8);          \
        }                                                                       \
        CP_COMMIT();                                                            \
    } while (0)

    ASYNC_CHUNK2(0, 0);
    CP_WAIT0();
    __syncthreads();

    for (int c = 0; c < 8; c++) {
        const uint32_t cur = (uint32_t)(c & 1) * BUFB;
        const uint32_t nxt = BUFB - cur;
        if (c < 7) ASYNC_CHUNK2((c + 1) * 32, nxt);

        const uint32_t AB = smb + cur + OFF_A;
        const uint32_t BB = smb + cur + OFF_B;

#pragma unroll
        for (int ks = 0; ks < 2; ks++) {
            const uint32_t kb = ks * 32;
            uint32_t bf[4][2];
#pragma unroll
            for (int np = 0; np < 2; np++) {
                uint32_t r0, r1, r2, r3;
                LDSM4(r0, r1, r2, r3, BB + boff + np * (16 * SROW) + kb);
                bf[2 * np][0] = r0; bf[2 * np][1] = r2;
                bf[2 * np + 1][0] = r1; bf[2 * np + 1][1] = r3;
            }
#pragma unroll
            for (int mf = 0; mf < 4; mf++) {
                uint32_t ah[4];
                LDSM4(ah[0], ah[1], ah[2], ah[3],
                      AB + aoff + mf * (16 * SROW) + kb);
#pragma unroll
                for (int nf = 0; nf < 4; nf++)
                    mma_fp16(acc[mf][nf], ah, bf[nf]);
            }
        }

        if (c < 7) CP_WAIT0();
        __syncthreads();
    }

#pragma unroll
    for (int nf = 0; nf < 4; nf++) {
        const int cc = col0 + wn0 + nf * 8 + (lane & 3) * 2;
        const float b0 = bias[cc], b1 = bias[cc + 1];
#pragma unroll
        for (int mf = 0; mf < 4; mf++) {
            const int r = row0 + wm0 + mf * 16 + (lane >> 2);
            float2 o0 = make_float2(acc[mf][nf][0] + b0, acc[mf][nf][1] + b1);
            float2 o1 = make_float2(acc[mf][nf][2] + b0, acc[mf][nf][3] + b1);
            *(float2*)(C + (size_t)r * 256 + cc) = o0;
            *(float2*)(C + (size_t)(r + 8) * 256 + cc) = o1;
        }
    }
}

// ---------------------------------------------------------------------------
// FP16-MMA attention (unchanged from R13).
// ---------------------------------------------------------------------------
#define HROW 88
#define HROWB (HROW * 2)

__global__ __launch_bounds__(128, 10) void attn_mma(const float* __restrict__ aw,
                                                    const int*   __restrict__ idx,
                                                    const float* __restrict__ wsel)
{
    __shared__ __half sA[64 * HROW];
    __shared__ __half sXT[32 * HROW];

    const int t    = threadIdx.x;
    const int bid  = blockIdx.x;
    const int blk  = bid & 255;
    const int b    = (bid >> 8) & 7;
    const int h    = bid >> 11;
    const int bh   = blk >> 4;
    const int bw   = blk & 15;
    const int lane = t & 31;
    const int warp = t >> 5;

    const uint32_t sAb  = smem_u32(sA);
    const uint32_t sXTb = smem_u32(sXT);

    const float* Ab = aw + (size_t)bid * 5120;
#pragma unroll
    for (int i = 0; i < 10; i++) {
        const int v = i * 128 + t;
        const int q = v / 20;
        const int m = v % 20;
        const float4 a = *(const float4*)(Ab + q * 80 + m * 4);
        __half2 h0 = __floats2half2_rn(a.x, a.y);
        __half2 h1 = __floats2half2_rn(a.z, a.w);
        uint2 hv;
        hv.x = *(uint32_t*)&h0;
        hv.y = *(uint32_t*)&h1;
        *(uint2*)(sA + q * HROW + m * 4) = hv;
    }

    const size_t xbase = (size_t)b * NTOK * 256 + h * 32;

#pragma unroll
    for (int i = 0; i < 4; i++) {
        const int v  = i * 128 + t;
        const int p  = v >> 3;
        const int dq = v & 7;
        const int r  = p >> 3, c = p & 7;
        const int sp = (bh * 8 + r) * 128 + bw * 8 + c;
        const uint2 hv = *(const uint2*)(g_xph + xbase + (size_t)sp * 256 + dq * 4);
        const __half2 h0 = *(const __half2*)&hv.x;
        const __half2 h1 = *(const __half2*)&hv.y;
        sXT[(dq * 4 + 0) * HROW + p] = __low2half(h0);
        sXT[(dq * 4 + 1) * HROW + p] = __high2half(h0);
        sXT[(dq * 4 + 2) * HROW + p] = __low2half(h1);
        sXT[(dq * 4 + 3) * HROW + p] = __high2half(h1);
    }
    {
        const int j    = t >> 3;
        const int dq   = t & 7;
        const int base = (b * 256 + blk) * 16 + j;
        const int tok  = idx[base];
        const float w  = wsel[base];
        const uint2 hv = *(const uint2*)(g_xph + xbase + (size_t)tok * 256 + dq * 4);
        const float2 f0 = __half22float2(*(const __half2*)&hv.x);
        const float2 f1 = __half22float2(*(const __half2*)&hv.y);
        sXT[(dq * 4 + 0) * HROW + 64 + j] = __float2half_rn(f0.x * w);
        sXT[(dq * 4 + 1) * HROW + 64 + j] = __float2half_rn(f0.y * w);
        sXT[(dq * 4 + 2) * HROW + 64 + j] = __float2half_rn(f1.x * w);
        sXT[(dq * 4 + 3) * HROW + 64 + j] = __float2half_rn(f1.y * w);
    }
    __syncthreads();

    const int m0 = warp << 4;
    const uint32_t aoff = sAb  + (uint32_t)(m0 + (lane & 15)) * HROWB +
                          ((lane >> 4) << 4);
    const uint32_t boff = sXTb + (uint32_t)(lane & 15) * HROWB +
                          ((lane >> 4) << 4);

    float acc[4][4];
#pragma unroll
    for (int i = 0; i < 4; i++)
#pragma unroll
        for (int j = 0; j < 4; j++) acc[i][j] = 0.f;

#pragma unroll
    for (int ks = 0; ks < 5; ks++) {
        const uint32_t kb = ks * 32;
        uint32_t ah[4], bf[4][2];
        LDSM4(ah[0], ah[1], ah[2], ah[3], aoff + kb);
#pragma unroll
        for (int np = 0; np < 2; np++) {
            uint32_t r0, r1, r2, r3;
            LDSM4(r0, r1, r2, r3, boff + np * (16 * HROWB) + kb);
            bf[2 * np][0] = r0; bf[2 * np][1] = r2;
            bf[2 * np + 1][0] = r1; bf[2 * np + 1][1] = r3;
        }
#pragma unroll
        for (int nf = 0; nf < 4; nf++)
            mma_fp16(acc[nf], ah, bf[nf]);
    }

    const int g  = lane >> 2;
    const int tg = lane & 3;
#pragma unroll
    for (int nf = 0; nf < 4; nf++) {
#pragma unroll
        for (int half = 0; half < 2; half++) {
            const int q  = m0 + g + half * 8;
            const int r  = q >> 3, c = q & 7;
            const int sp = (bh * 8 + r) * 128 + bw * 8 + c;
            __half2 o = __floats2half2_rn(acc[nf][half * 2 + 0],
                                          acc[nf][half * 2 + 1]);
            *(uint32_t*)(g_yh + xbase + (size_t)sp * 256 + nf * 8 + tg * 2) =
                *(uint32_t*)&o;
        }
    }
}

// ===========================================================================
extern "C" void kernel_launch(void* const* d_in, const int* in_sizes, int n_in,
                              void* d_out, int out_size)
{
    const float* x    = (const float*)d_in[0];
    const float* aw   = (const float*)d_in[1];
    const int*   idx  = (const int*)d_in[2];
    const float* wsel = (const float*)d_in[3];
    const float* Win  = (const float*)d_in[4];
    const float* bin  = (const float*)d_in[5];
    const float* Wout = (const float*)d_in[6];
    const float* bout = (const float*)d_in[7];
    float* out = (float*)d_out;

    __half *xph, *yh, *wt1, *wt2;
    cudaGetSymbolAddress((void**)&xph, g_xph);
    cudaGetSymbolAddress((void**)&yh, g_yh);
    cudaGetSymbolAddress((void**)&wt1, g_wt1);
    cudaGetSymbolAddress((void**)&wt2, g_wt2);

    cudaFuncSetAttribute(gemm_f32in_f16out,
                         cudaFuncAttributeMaxDynamicSharedMemorySize, GEMM_SMEM);
    cudaFuncSetAttribute(gemm_f16in_f32out,
                         cudaFuncAttributeMaxDynamicSharedMemorySize, GEMM_SMEM);

    transpose_both<<<128, 256>>>(Win, wt1, Wout, wt2);

    gemm_f32in_f16out<<<dim3(2, 1024), 256, GEMM_SMEM>>>(x, wt1, bin, xph);
    attn_mma<<<16384, 128>>>(aw, idx, wsel);
    gemm_f16in_f32out<<<dim3(2, 1024), 256, GEMM_SMEM>>>(yh, wt2, bout, out);
}

// round 16
// speedup vs baseline: 1.2108x; 1.2108x over previous
#include <cuda_runtime.h>
#include <cuda_fp16.h>
#include <cstdint>

#define NTOK 16384

// Scratch (allocation-free rule: __device__ globals)
__device__ __half g_xph[33554432];  // x @ W_in, fp16
__device__ __half g_yh[33554432];   // attention output, fp16
__device__ __half g_wt1[65536];     // W_in^T  [n][k], fp16
__device__ __half g_wt2[65536];     // W_out^T [n][k], fp16

// ---------------------------------------------------------------------------
__device__ __forceinline__ uint32_t smem_u32(const void* p) {
    uint32_t a;
    asm("{ .reg .u64 t; cvta.to.shared.u64 t, %1; cvt.u32.u64 %0, t; }"
        : "=r"(a) : "l"(p));
    return a;
}
__device__ __forceinline__ void mma_fp16(float* d, const uint32_t* a,
                                         const uint32_t* b) {
    asm volatile(
        "mma.sync.aligned.m16n8k16.row.col.f32.f16.f16.f32 "
        "{%0,%1,%2,%3}, {%4,%5,%6,%7}, {%8,%9}, {%0,%1,%2,%3};"
        : "+f"(d[0]), "+f"(d[1]), "+f"(d[2]), "+f"(d[3])
        : "r"(a[0]), "r"(a[1]), "r"(a[2]), "r"(a[3]), "r"(b[0]), "r"(b[1]));
}
#define LDSM4(R0, R1, R2, R3, addr) \
    asm volatile("ldmatrix.sync.aligned.m8n8.x4.shared.b16 {%0,%1,%2,%3}, [%4];" \
                 : "=r"(R0), "=r"(R1), "=r"(R2), "=r"(R3) : "r"(addr))
#define CP_ASYNC16(dst, src) \
    asm volatile("cp.async.ca.shared.global [%0], [%1], 16;" \
                 :: "r"(dst), "l"(src))
#define CP_COMMIT() asm volatile("cp.async.commit_group;")
#define CP_WAIT0()  asm volatile("cp.async.wait_group 0;")

// ---------------------------------------------------------------------------
// Merged transpose + fp16 convert for both weight matrices.
// ---------------------------------------------------------------------------
__global__ void transpose_both(const float* __restrict__ W1,
                               __half* __restrict__ T1,
                               const float* __restrict__ W2,
                               __half* __restrict__ T2)
{
    __shared__ float tile[32][33];
    const int sel = blockIdx.x >> 6;
    const int bb  = blockIdx.x & 63;
    const float* W = sel ? W2 : W1;
    __half*      T = sel ? T2 : T1;
    const int bx = (bb & 7) << 5;
    const int by = (bb >> 3) << 5;
    const int tx = threadIdx.x & 31;
    const int ty = threadIdx.x >> 5;
#pragma unroll
    for (int i = 0; i < 32; i += 8)
        tile[ty + i][tx] = W[(by + ty + i) * 256 + bx + tx];
    __syncthreads();
#pragma unroll
    for (int i = 0; i < 32; i += 8)
        T[(bx + ty + i) * 256 + by + tx] = __float2half_rn(tile[tx][ty + i]);
}

// ---------------------------------------------------------------------------
// GEMM geometry: CTA tile 128M x 64N, BK=32, 256 thr, 8 warps (4M x 2N),
// warp tile 32x32 -> 32 accumulators/thread (~64 regs, 4 CTAs/SM natural).
// ---------------------------------------------------------------------------
#define SROW 80                    // bytes per smem row (32 fp16 + 8 pad)
#define OFF_A 0
#define OFF_B 10240                // A tile: 128 rows
#define BUFB  15360                // A (10240) + B (64 rows * 80 = 5120)
#define GEMM_SMEM (2 * BUFB)       // 30720

// === Variant 1: A fp32 in (reg path + cvt), B fp16 cp.async, C fp16 out ====
__global__ __launch_bounds__(256) void gemm_f32in_f16out(
    const float* __restrict__ A, const __half* __restrict__ Bt,
    const float* __restrict__ bias, __half* __restrict__ C)
{
    extern __shared__ char sm[];
    const uint32_t smb = smem_u32(sm);
    const int t    = threadIdx.x;
    const int lane = t & 31;
    const int warp = t >> 5;
    const int wm0  = (warp >> 1) * 32;   // 4 M-groups
    const int wn0  = (warp & 1) * 32;    // 2 N-groups
    const int row0 = blockIdx.y << 7;
    const int col0 = blockIdx.x << 6;    // 64-wide N tiles

    const int lr = t >> 3;          // A rows i*32+lr
    const int lk = (t & 7) << 2;    // A k-offset (4 floats)
    const int cr = t >> 2;          // B rows (0..63)
    const int cs = t & 3;           // 16B segment

    float acc[2][4][4];
#pragma unroll
    for (int i = 0; i < 2; i++)
#pragma unroll
        for (int j = 0; j < 4; j++)
#pragma unroll
            for (int k = 0; k < 4; k++) acc[i][j][k] = 0.f;

    float4 pa[4];

    const uint32_t aoff = (uint32_t)(wm0 + (lane & 15)) * SROW + ((lane >> 4) << 4);
    const uint32_t boff = (uint32_t)(wn0 + (lane & 15)) * SROW + ((lane >> 4) << 4);

#define B_ASYNC1(k0, bufoff)                                                    \
    do {                                                                        \
        CP_ASYNC16(smb + (bufoff) + OFF_B + (uint32_t)cr * SROW + cs * 16,      \
                   Bt + (size_t)(col0 + cr) * 256 + (k0) + cs * 8);             \
        CP_COMMIT();                                                            \
    } while (0)

#define A_LOAD1(k0)                                                             \
    do {                                                                        \
        _Pragma("unroll")                                                       \
        for (int i = 0; i < 4; i++)                                             \
            pa[i] = *(const float4*)(A + (size_t)(row0 + i * 32 + lr) * 256 +   \
                                     (k0) + lk);                                \
    } while (0)

#define A_STORE1(bufoff)                                                        \
    do {                                                                        \
        char* base = sm + (bufoff);                                             \
        _Pragma("unroll")                                                       \
        for (int i = 0; i < 4; i++) {                                           \
            const int r = i * 32 + lr;                                          \
            const uint32_t off = (uint32_t)r * SROW + ((t & 7) << 3);           \
            uint2 hh;                                                           \
            __half2 h0 = __floats2half2_rn(pa[i].x, pa[i].y);                   \
            __half2 h1 = __floats2half2_rn(pa[i].z, pa[i].w);                   \
            hh.x = *(uint32_t*)&h0;                                             \
            hh.y = *(uint32_t*)&h1;                                             \
            *(uint2*)(base + OFF_A + off) = hh;                                 \
        }                                                                       \
    } while (0)

    A_LOAD1(0);
    B_ASYNC1(0, 0);
    A_STORE1(0);
    CP_WAIT0();
    __syncthreads();

    for (int c = 0; c < 8; c++) {
        const uint32_t cur = (uint32_t)(c & 1) * BUFB;
        const uint32_t nxt = BUFB - cur;
        if (c < 7) {
            B_ASYNC1((c + 1) * 32, nxt);
            A_LOAD1((c + 1) * 32);
        }

        const uint32_t AB = smb + cur + OFF_A;
        const uint32_t BB = smb + cur + OFF_B;

#pragma unroll
        for (int ks = 0; ks < 2; ks++) {
            const uint32_t kb = ks * 32;
            uint32_t bf[4][2];
#pragma unroll
            for (int np = 0; np < 2; np++) {
                uint32_t r0, r1, r2, r3;
                LDSM4(r0, r1, r2, r3, BB + boff + np * (16 * SROW) + kb);
                bf[2 * np][0] = r0; bf[2 * np][1] = r2;
                bf[2 * np + 1][0] = r1; bf[2 * np + 1][1] = r3;
            }
#pragma unroll
            for (int mf = 0; mf < 2; mf++) {
                uint32_t ah[4];
                LDSM4(ah[0], ah[1], ah[2], ah[3],
                      AB + aoff + mf * (16 * SROW) + kb);
#pragma unroll
                for (int nf = 0; nf < 4; nf++)
                    mma_fp16(acc[mf][nf], ah, bf[nf]);
            }
        }

        if (c < 7) {
            A_STORE1(nxt);
            CP_WAIT0();
        }
        __syncthreads();
    }

#pragma unroll
    for (int nf = 0; nf < 4; nf++) {
        const int cc = col0 + wn0 + nf * 8 + (lane & 3) * 2;
        const float b0 = bias[cc], b1 = bias[cc + 1];
#pragma unroll
        for (int mf = 0; mf < 2; mf++) {
            const int r = row0 + wm0 + mf * 16 + (lane >> 2);
            __half2 o0 = __floats2half2_rn(acc[mf][nf][0] + b0, acc[mf][nf][1] + b1);
            __half2 o1 = __floats2half2_rn(acc[mf][nf][2] + b0, acc[mf][nf][3] + b1);
            *(uint32_t*)(C + (size_t)r * 256 + cc) = *(uint32_t*)&o0;
            *(uint32_t*)(C + (size_t)(r + 8) * 256 + cc) = *(uint32_t*)&o1;
        }
    }
}

// === Variant 2: A fp16 in (cp.async both operands), C fp32 out =============
__global__ __launch_bounds__(256) void gemm_f16in_f32out(
    const __half* __restrict__ A, const __half* __restrict__ Bt,
    const float* __restrict__ bias, float* __restrict__ C)
{
    extern __shared__ char sm[];
    const uint32_t smb = smem_u32(sm);
    const int t    = threadIdx.x;
    const int lane = t & 31;
    const int warp = t >> 5;
    const int wm0  = (warp >> 1) * 32;
    const int wn0  = (warp & 1) * 32;
    const int row0 = blockIdx.y << 7;
    const int col0 = blockIdx.x << 6;

    const int cr = t >> 2;          // 0..63
    const int cs = t & 3;

    float acc[2][4][4];
#pragma unroll
    for (int i = 0; i < 2; i++)
#pragma unroll
        for (int j = 0; j < 4; j++)
#pragma unroll
            for (int k = 0; k < 4; k++) acc[i][j][k] = 0.f;

    const uint32_t aoff = (uint32_t)(wm0 + (lane & 15)) * SROW + ((lane >> 4) << 4);
    const uint32_t boff = (uint32_t)(wn0 + (lane & 15)) * SROW + ((lane >> 4) << 4);

#define ASYNC_CHUNK2(k0, bufoff)                                                \
    do {                                                                        \
        _Pragma("unroll")                                                       \
        for (int i = 0; i < 2; i++) {                                           \
            const int r = i * 64 + cr;                                          \
            CP_ASYNC16(smb + (bufoff) + OFF_A + (uint32_t)r * SROW + cs * 16,   \
                       A + (size_t)(row0 + r) * 256 + (k0) + cs * 8);           \
        }                                                                       \
        CP_ASYNC16(smb + (bufoff) + OFF_B + (uint32_t)cr * SROW + cs * 16,      \
                   Bt + (size_t)(col0 + cr) * 256 + (k0) + cs * 8);             \
        CP_COMMIT();                                                            \
    } while (0)

    ASYNC_CHUNK2(0, 0);
    CP_WAIT0();
    __syncthreads();

    for (int c = 0; c < 8; c++) {
        const uint32_t cur = (uint32_t)(c & 1) * BUFB;
        const uint32_t nxt = BUFB - cur;
        if (c < 7) ASYNC_CHUNK2((c + 1) * 32, nxt);

        const uint32_t AB = smb + cur + OFF_A;
        const uint32_t BB = smb + cur + OFF_B;

#pragma unroll
        for (int ks = 0; ks < 2; ks++) {
            const uint32_t kb = ks * 32;
            uint32_t bf[4][2];
#pragma unroll
            for (int np = 0; np < 2; np++) {
                uint32_t r0, r1, r2, r3;
                LDSM4(r0, r1, r2, r3, BB + boff + np * (16 * SROW) + kb);
                bf[2 * np][0] = r0; bf[2 * np][1] = r2;
                bf[2 * np + 1][0] = r1; bf[2 * np + 1][1] = r3;
            }
#pragma unroll
            for (int mf = 0; mf < 2; mf++) {
                uint32_t ah[4];
                LDSM4(ah[0], ah[1], ah[2], ah[3],
                      AB + aoff + mf * (16 * SROW) + kb);
#pragma unroll
                for (int nf = 0; nf < 4; nf++)
                    mma_fp16(acc[mf][nf], ah, bf[nf]);
            }
        }

        if (c < 7) CP_WAIT0();
        __syncthreads();
    }

#pragma unroll
    for (int nf = 0; nf < 4; nf++) {
        const int cc = col0 + wn0 + nf * 8 + (lane & 3) * 2;
        const float b0 = bias[cc], b1 = bias[cc + 1];
#pragma unroll
        for (int mf = 0; mf < 2; mf++) {
            const int r = row0 + wm0 + mf * 16 + (lane >> 2);
            float2 o0 = make_float2(acc[mf][nf][0] + b0, acc[mf][nf][1] + b1);
            float2 o1 = make_float2(acc[mf][nf][2] + b0, acc[mf][nf][3] + b1);
            *(float2*)(C + (size_t)r * 256 + cc) = o0;
            *(float2*)(C + (size_t)(r + 8) * 256 + cc) = o1;
        }
    }
}

// ---------------------------------------------------------------------------
// FP16-MMA attention (unchanged from R13).
// ---------------------------------------------------------------------------
#define HROW 88
#define HROWB (HROW * 2)

__global__ __launch_bounds__(128, 10) void attn_mma(const float* __restrict__ aw,
                                                    const int*   __restrict__ idx,
                                                    const float* __restrict__ wsel)
{
    __shared__ __half sA[64 * HROW];
    __shared__ __half sXT[32 * HROW];

    const int t    = threadIdx.x;
    const int bid  = blockIdx.x;
    const int blk  = bid & 255;
    const int b    = (bid >> 8) & 7;
    const int h    = bid >> 11;
    const int bh   = blk >> 4;
    const int bw   = blk & 15;
    const int lane = t & 31;
    const int warp = t >> 5;

    const uint32_t sAb  = smem_u32(sA);
    const uint32_t sXTb = smem_u32(sXT);

    const float* Ab = aw + (size_t)bid * 5120;
#pragma unroll
    for (int i = 0; i < 10; i++) {
        const int v = i * 128 + t;
        const int q = v / 20;
        const int m = v % 20;
        const float4 a = *(const float4*)(Ab + q * 80 + m * 4);
        __half2 h0 = __floats2half2_rn(a.x, a.y);
        __half2 h1 = __floats2half2_rn(a.z, a.w);
        uint2 hv;
        hv.x = *(uint32_t*)&h0;
        hv.y = *(uint32_t*)&h1;
        *(uint2*)(sA + q * HROW + m * 4) = hv;
    }

    const size_t xbase = (size_t)b * NTOK * 256 + h * 32;

#pragma unroll
    for (int i = 0; i < 4; i++) {
        const int v  = i * 128 + t;
        const int p  = v >> 3;
        const int dq = v & 7;
        const int r  = p >> 3, c = p & 7;
        const int sp = (bh * 8 + r) * 128 + bw * 8 + c;
        const uint2 hv = *(const uint2*)(g_xph + xbase + (size_t)sp * 256 + dq * 4);
        const __half2 h0 = *(const __half2*)&hv.x;
        const __half2 h1 = *(const __half2*)&hv.y;
        sXT[(dq * 4 + 0) * HROW + p] = __low2half(h0);
        sXT[(dq * 4 + 1) * HROW + p] = __high2half(h0);
        sXT[(dq * 4 + 2) * HROW + p] = __low2half(h1);
        sXT[(dq * 4 + 3) * HROW + p] = __high2half(h1);
    }
    {
        const int j    = t >> 3;
        const int dq   = t & 7;
        const int base = (b * 256 + blk) * 16 + j;
        const int tok  = idx[base];
        const float w  = wsel[base];
        const uint2 hv = *(const uint2*)(g_xph + xbase + (size_t)tok * 256 + dq * 4);
        const float2 f0 = __half22float2(*(const __half2*)&hv.x);
        const float2 f1 = __half22float2(*(const __half2*)&hv.y);
        sXT[(dq * 4 + 0) * HROW + 64 + j] = __float2half_rn(f0.x * w);
        sXT[(dq * 4 + 1) * HROW + 64 + j] = __float2half_rn(f0.y * w);
        sXT[(dq * 4 + 2) * HROW + 64 + j] = __float2half_rn(f1.x * w);
        sXT[(dq * 4 + 3) * HROW + 64 + j] = __float2half_rn(f1.y * w);
    }
    __syncthreads();

    const int m0 = warp << 4;
    const uint32_t aoff = sAb  + (uint32_t)(m0 + (lane & 15)) * HROWB +
                          ((lane >> 4) << 4);
    const uint32_t boff = sXTb + (uint32_t)(lane & 15) * HROWB +
                          ((lane >> 4) << 4);

    float acc[4][4];
#pragma unroll
    for (int i = 0; i < 4; i++)
#pragma unroll
        for (int j = 0; j < 4; j++) acc[i][j] = 0.f;

#pragma unroll
    for (int ks = 0; ks < 5; ks++) {
        const uint32_t kb = ks * 32;
        uint32_t ah[4], bf[4][2];
        LDSM4(ah[0], ah[1], ah[2], ah[3], aoff + kb);
#pragma unroll
        for (int np = 0; np < 2; np++) {
            uint32_t r0, r1, r2, r3;
            LDSM4(r0, r1, r2, r3, boff + np * (16 * HROWB) + kb);
            bf[2 * np][0] = r0; bf[2 * np][1] = r2;
            bf[2 * np + 1][0] = r1; bf[2 * np + 1][1] = r3;
        }
#pragma unroll
        for (int nf = 0; nf < 4; nf++)
            mma_fp16(acc[nf], ah, bf[nf]);
    }

    const int g  = lane >> 2;
    const int tg = lane & 3;
#pragma unroll
    for (int nf = 0; nf < 4; nf++) {
#pragma unroll
        for (int half = 0; half < 2; half++) {
            const int q  = m0 + g + half * 8;
            const int r  = q >> 3, c = q & 7;
            const int sp = (bh * 8 + r) * 128 + bw * 8 + c;
            __half2 o = __floats2half2_rn(acc[nf][half * 2 + 0],
                                          acc[nf][half * 2 + 1]);
            *(uint32_t*)(g_yh + xbase + (size_t)sp * 256 + nf * 8 + tg * 2) =
                *(uint32_t*)&o;
        }
    }
}

// ===========================================================================
extern "C" void kernel_launch(void* const* d_in, const int* in_sizes, int n_in,
                              void* d_out, int out_size)
{
    const float* x    = (const float*)d_in[0];
    const float* aw   = (const float*)d_in[1];
    const int*   idx  = (const int*)d_in[2];
    const float* wsel = (const float*)d_in[3];
    const float* Win  = (const float*)d_in[4];
    const float* bin  = (const float*)d_in[5];
    const float* Wout = (const float*)d_in[6];
    const float* bout = (const float*)d_in[7];
    float* out = (float*)d_out;

    __half *xph, *yh, *wt1, *wt2;
    cudaGetSymbolAddress((void**)&xph, g_xph);
    cudaGetSymbolAddress((void**)&yh, g_yh);
    cudaGetSymbolAddress((void**)&wt1, g_wt1);
    cudaGetSymbolAddress((void**)&wt2, g_wt2);

    cudaFuncSetAttribute(gemm_f32in_f16out,
                         cudaFuncAttributeMaxDynamicSharedMemorySize, GEMM_SMEM);
    cudaFuncSetAttribute(gemm_f16in_f32out,
                         cudaFuncAttributeMaxDynamicSharedMemorySize, GEMM_SMEM);

    transpose_both<<<128, 256>>>(Win, wt1, Wout, wt2);

    gemm_f32in_f16out<<<dim3(4, 1024), 256, GEMM_SMEM>>>(x, wt1, bin, xph);
    attn_mma<<<16384, 128>>>(aw, idx, wsel);
    gemm_f16in_f32out<<<dim3(4, 1024), 256, GEMM_SMEM>>>(yh, wt2, bout, out);
}

// round 17
// speedup vs baseline: 1.4500x; 1.1976x over previous
#include <cuda_runtime.h>
#include <cuda_fp16.h>
#include <cstdint>

#define NTOK 16384

// Scratch (allocation-free rule: __device__ globals)
__device__ __half g_xph[33554432];  // x @ W_in, fp16
__device__ __half g_yh[33554432];   // attention output, fp16
__device__ __half g_wt1[65536];     // W_in^T  [n][k], fp16
__device__ __half g_wt2[65536];     // W_out^T [n][k], fp16

// ---------------------------------------------------------------------------
__device__ __forceinline__ uint32_t smem_u32(const void* p) {
    uint32_t a;
    asm("{ .reg .u64 t; cvta.to.shared.u64 t, %1; cvt.u32.u64 %0, t; }"
        : "=r"(a) : "l"(p));
    return a;
}
__device__ __forceinline__ void mma_fp16(float* d, const uint32_t* a,
                                         const uint32_t* b) {
    asm volatile(
        "mma.sync.aligned.m16n8k16.row.col.f32.f16.f16.f32 "
        "{%0,%1,%2,%3}, {%4,%5,%6,%7}, {%8,%9}, {%0,%1,%2,%3};"
        : "+f"(d[0]), "+f"(d[1]), "+f"(d[2]), "+f"(d[3])
        : "r"(a[0]), "r"(a[1]), "r"(a[2]), "r"(a[3]), "r"(b[0]), "r"(b[1]));
}
#define LDSM4(R0, R1, R2, R3, addr) \
    asm volatile("ldmatrix.sync.aligned.m8n8.x4.shared.b16 {%0,%1,%2,%3}, [%4];" \
                 : "=r"(R0), "=r"(R1), "=r"(R2), "=r"(R3) : "r"(addr))
#define CP_ASYNC16(dst, src) \
    asm volatile("cp.async.ca.shared.global [%0], [%1], 16;" \
                 :: "r"(dst), "l"(src))
#define CP_COMMIT() asm volatile("cp.async.commit_group;")
#define CP_WAIT0()  asm volatile("cp.async.wait_group 0;")
#define CP_WAIT1()  asm volatile("cp.async.wait_group 1;")

// ---------------------------------------------------------------------------
// Merged transpose + fp16 convert for both weight matrices.
// ---------------------------------------------------------------------------
__global__ void transpose_both(const float* __restrict__ W1,
                               __half* __restrict__ T1,
                               const float* __restrict__ W2,
                               __half* __restrict__ T2)
{
    __shared__ float tile[32][33];
    const int sel = blockIdx.x >> 6;
    const int bb  = blockIdx.x & 63;
    const float* W = sel ? W2 : W1;
    __half*      T = sel ? T2 : T1;
    const int bx = (bb & 7) << 5;
    const int by = (bb >> 3) << 5;
    const int tx = threadIdx.x & 31;
    const int ty = threadIdx.x >> 5;
#pragma unroll
    for (int i = 0; i < 32; i += 8)
        tile[ty + i][tx] = W[(by + ty + i) * 256 + bx + tx];
    __syncthreads();
#pragma unroll
    for (int i = 0; i < 32; i += 8)
        T[(bx + ty + i) * 256 + by + tx] = __float2half_rn(tile[tx][ty + i]);
}

// ---------------------------------------------------------------------------
// GEMM geometry (R13): CTA 128x128, BK=32, 256 thr, 8 warps (2M x 4N)
// ---------------------------------------------------------------------------
#define SROW 80                    // bytes per smem row (32 fp16 + 8 pad)
#define OFF_A 0
#define OFF_B 10240
#define BUFB  20480
#define GEMM1_SMEM (2 * BUFB)      // double buffer (A reg path)
#define GEMM2_SMEM (3 * BUFB)      // triple buffer (pure cp.async)

// === Variant 1: A fp32 in (reg path + cvt), B fp16 cp.async, C fp16 out ====
// (exact R13 structure — proven 246.4 baseline)
__global__ __launch_bounds__(256) void gemm_f32in_f16out(
    const float* __restrict__ A, const __half* __restrict__ Bt,
    const float* __restrict__ bias, __half* __restrict__ C)
{
    extern __shared__ char sm[];
    const uint32_t smb = smem_u32(sm);
    const int t    = threadIdx.x;
    const int lane = t & 31;
    const int warp = t >> 5;
    const int wm0  = (warp >> 2) * 64;
    const int wn0  = (warp & 3) * 32;
    const int row0 = blockIdx.y << 7;
    const int col0 = blockIdx.x << 7;

    const int lr = t >> 3;
    const int lk = (t & 7) << 2;
    const int cr = t >> 2;
    const int cs = t & 3;

    float acc[4][4][4];
#pragma unroll
    for (int i = 0; i < 4; i++)
#pragma unroll
        for (int j = 0; j < 4; j++)
#pragma unroll
            for (int k = 0; k < 4; k++) acc[i][j][k] = 0.f;

    float4 pa[4];

    const uint32_t aoff = (uint32_t)(wm0 + (lane & 15)) * SROW + ((lane >> 4) << 4);
    const uint32_t boff = (uint32_t)(wn0 + (lane & 15)) * SROW + ((lane >> 4) << 4);

#define B_ASYNC1(k0, bufoff)                                                    \
    do {                                                                        \
        _Pragma("unroll")                                                       \
        for (int i = 0; i < 2; i++) {                                           \
            const int r = i * 64 + cr;                                          \
            CP_ASYNC16(smb + (bufoff) + OFF_B + (uint32_t)r * SROW + cs * 16,   \
                       Bt + (size_t)(col0 + r) * 256 + (k0) + cs * 8);          \
        }                                                                       \
        CP_COMMIT();                                                            \
    } while (0)

#define A_LOAD1(k0)                                                             \
    do {                                                                        \
        _Pragma("unroll")                                                       \
        for (int i = 0; i < 4; i++)                                             \
            pa[i] = *(const float4*)(A + (size_t)(row0 + i * 32 + lr) * 256 +   \
                                     (k0) + lk);                                \
    } while (0)

#define A_STORE1(bufoff)                                                        \
    do {                                                                        \
        char* base = sm + (bufoff);                                             \
        _Pragma("unroll")                                                       \
        for (int i = 0; i < 4; i++) {                                           \
            const int r = i * 32 + lr;                                          \
            const uint32_t off = (uint32_t)r * SROW + ((t & 7) << 3);           \
            uint2 hh;                                                           \
            __half2 h0 = __floats2half2_rn(pa[i].x, pa[i].y);                   \
            __half2 h1 = __floats2half2_rn(pa[i].z, pa[i].w);                   \
            hh.x = *(uint32_t*)&h0;                                             \
            hh.y = *(uint32_t*)&h1;                                             \
            *(uint2*)(base + OFF_A + off) = hh;                                 \
        }                                                                       \
    } while (0)

    A_LOAD1(0);
    B_ASYNC1(0, 0);
    A_STORE1(0);
    CP_WAIT0();
    __syncthreads();

    for (int c = 0; c < 8; c++) {
        const uint32_t cur = (uint32_t)(c & 1) * BUFB;
        const uint32_t nxt = BUFB - cur;
        if (c < 7) {
            B_ASYNC1((c + 1) * 32, nxt);
            A_LOAD1((c + 1) * 32);
        }

        const uint32_t AB = smb + cur + OFF_A;
        const uint32_t BB = smb + cur + OFF_B;

#pragma unroll
        for (int ks = 0; ks < 2; ks++) {
            const uint32_t kb = ks * 32;
            uint32_t ah[4][4], bf[4][2];
#pragma unroll
            for (int mf = 0; mf < 4; mf++)
                LDSM4(ah[mf][0], ah[mf][1], ah[mf][2], ah[mf][3],
                      AB + aoff + mf * (16 * SROW) + kb);
#pragma unroll
            for (int np = 0; np < 2; np++) {
                uint32_t r0, r1, r2, r3;
                LDSM4(r0, r1, r2, r3, BB + boff + np * (16 * SROW) + kb);
                bf[2 * np][0] = r0; bf[2 * np][1] = r2;
                bf[2 * np + 1][0] = r1; bf[2 * np + 1][1] = r3;
            }
#pragma unroll
            for (int mf = 0; mf < 4; mf++)
#pragma unroll
                for (int nf = 0; nf < 4; nf++)
                    mma_fp16(acc[mf][nf], ah[mf], bf[nf]);
        }

        if (c < 7) {
            A_STORE1(nxt);
            CP_WAIT0();
        }
        __syncthreads();
    }

#pragma unroll
    for (int nf = 0; nf < 4; nf++) {
        const int cc = col0 + wn0 + nf * 8 + (lane & 3) * 2;
        const float b0 = bias[cc], b1 = bias[cc + 1];
#pragma unroll
        for (int mf = 0; mf < 4; mf++) {
            const int r = row0 + wm0 + mf * 16 + (lane >> 2);
            __half2 o0 = __floats2half2_rn(acc[mf][nf][0] + b0, acc[mf][nf][1] + b1);
            __half2 o1 = __floats2half2_rn(acc[mf][nf][2] + b0, acc[mf][nf][3] + b1);
            *(uint32_t*)(C + (size_t)r * 256 + cc) = *(uint32_t*)&o0;
            *(uint32_t*)(C + (size_t)(r + 8) * 256 + cc) = *(uint32_t*)&o1;
        }
    }
}

// === Variant 2: A fp16 in, C fp32 out — TRIPLE-buffered cp.async pipeline ===
__global__ __launch_bounds__(256) void gemm_f16in_f32out(
    const __half* __restrict__ A, const __half* __restrict__ Bt,
    const float* __restrict__ bias, float* __restrict__ C)
{
    extern __shared__ char sm[];
    const uint32_t smb = smem_u32(sm);
    const int t    = threadIdx.x;
    const int lane = t & 31;
    const int warp = t >> 5;
    const int wm0  = (warp >> 2) * 64;
    const int wn0  = (warp & 3) * 32;
    const int row0 = blockIdx.y << 7;
    const int col0 = blockIdx.x << 7;

    const int cr = t >> 2;
    const int cs = t & 3;

    float acc[4][4][4];
#pragma unroll
    for (int i = 0; i < 4; i++)
#pragma unroll
        for (int j = 0; j < 4; j++)
#pragma unroll
            for (int k = 0; k < 4; k++) acc[i][j][k] = 0.f;

    const uint32_t aoff = (uint32_t)(wm0 + (lane & 15)) * SROW + ((lane >> 4) << 4);
    const uint32_t boff = (uint32_t)(wn0 + (lane & 15)) * SROW + ((lane >> 4) << 4);

#define ASYNC_CHUNK2(k0, bufoff)                                                \
    do {                                                                        \
        _Pragma("unroll")                                                       \
        for (int i = 0; i < 2; i++) {                                           \
            const int r = i * 64 + cr;                                          \
            const uint32_t off = (uint32_t)r * SROW + cs * 16;                  \
            CP_ASYNC16(smb + (bufoff) + OFF_A + off,                            \
                       A + (size_t)(row0 + r) * 256 + (k0) + cs * 8);           \
            CP_ASYNC16(smb + (bufoff) + OFF_B + off,                            \
                       Bt + (size_t)(col0 + r) * 256 + (k0) + cs * 8);          \
        }                                                                       \
        CP_COMMIT();                                                            \
    } while (0)

    // Prologue: two chunks in flight; wait for chunk 0 only.
    ASYNC_CHUNK2(0, 0);
    ASYNC_CHUNK2(32, BUFB);
    CP_WAIT1();
    __syncthreads();

    uint32_t bufoff[3] = {0, BUFB, 2 * BUFB};

    for (int c = 0; c < 8; c++) {
        const uint32_t cur = bufoff[c % 3];
        // Prefetch chunk c+2 into the buffer freed at iteration c-1.
        if (c + 2 < 8) ASYNC_CHUNK2((c + 2) * 32, bufoff[(c + 2) % 3]);

        const uint32_t AB = smb + cur + OFF_A;
        const uint32_t BB = smb + cur + OFF_B;

#pragma unroll
        for (int ks = 0; ks < 2; ks++) {
            const uint32_t kb = ks * 32;
            uint32_t ah[4][4], bf[4][2];
#pragma unroll
            for (int mf = 0; mf < 4; mf++)
                LDSM4(ah[mf][0], ah[mf][1], ah[mf][2], ah[mf][3],
                      AB + aoff + mf * (16 * SROW) + kb);
#pragma unroll
            for (int np = 0; np < 2; np++) {
                uint32_t r0, r1, r2, r3;
                LDSM4(r0, r1, r2, r3, BB + boff + np * (16 * SROW) + kb);
                bf[2 * np][0] = r0; bf[2 * np][1] = r2;
                bf[2 * np + 1][0] = r1; bf[2 * np + 1][1] = r3;
            }
#pragma unroll
            for (int mf = 0; mf < 4; mf++)
#pragma unroll
                for (int nf = 0; nf < 4; nf++)
                    mma_fp16(acc[mf][nf], ah[mf], bf[nf]);
        }

        if (c < 7) {
            // chunk c+1 must be resident; chunk c+2 may still be in flight.
            if (c + 2 < 8) CP_WAIT1(); else CP_WAIT0();
            __syncthreads();
        }
    }

#pragma unroll
    for (int nf = 0; nf < 4; nf++) {
        const int cc = col0 + wn0 + nf * 8 + (lane & 3) * 2;
        const float b0 = bias[cc], b1 = bias[cc + 1];
#pragma unroll
        for (int mf = 0; mf < 4; mf++) {
            const int r = row0 + wm0 + mf * 16 + (lane >> 2);
            float2 o0 = make_float2(acc[mf][nf][0] + b0, acc[mf][nf][1] + b1);
            float2 o1 = make_float2(acc[mf][nf][2] + b0, acc[mf][nf][3] + b1);
            *(float2*)(C + (size_t)r * 256 + cc) = o0;
            *(float2*)(C + (size_t)(r + 8) * 256 + cc) = o1;
        }
    }
}

// ---------------------------------------------------------------------------
// FP16-MMA attention (R13 structure; local-token loads widened to uint4).
// ---------------------------------------------------------------------------
#define HROW 88
#define HROWB (HROW * 2)

__global__ __launch_bounds__(128, 10) void attn_mma(const float* __restrict__ aw,
                                                    const int*   __restrict__ idx,
                                                    const float* __restrict__ wsel)
{
    __shared__ __half sA[64 * HROW];
    __shared__ __half sXT[32 * HROW];

    const int t    = threadIdx.x;
    const int bid  = blockIdx.x;
    const int blk  = bid & 255;
    const int b    = (bid >> 8) & 7;
    const int h    = bid >> 11;
    const int bh   = blk >> 4;
    const int bw   = blk & 15;
    const int lane = t & 31;
    const int warp = t >> 5;

    const uint32_t sAb  = smem_u32(sA);
    const uint32_t sXTb = smem_u32(sXT);

    const float* Ab = aw + (size_t)bid * 5120;
#pragma unroll
    for (int i = 0; i < 10; i++) {
        const int v = i * 128 + t;
        const int q = v / 20;
        const int m = v % 20;
        const float4 a = *(const float4*)(Ab + q * 80 + m * 4);
        __half2 h0 = __floats2half2_rn(a.x, a.y);
        __half2 h1 = __floats2half2_rn(a.z, a.w);
        uint2 hv;
        hv.x = *(uint32_t*)&h0;
        hv.y = *(uint32_t*)&h1;
        *(uint2*)(sA + q * HROW + m * 4) = hv;
    }

    const size_t xbase = (size_t)b * NTOK * 256 + h * 32;

    // ---- stage X^T: local 64 tokens via uint4 (8 halves), 2/thread
#pragma unroll
    for (int i = 0; i < 2; i++) {
        const int v  = i * 128 + t;      // [0,256)
        const int p  = v >> 2;           // token 0..63
        const int q8 = v & 3;            // which 8-half group (ch 8*q8..)
        const int r  = p >> 3, c = p & 7;
        const int sp = (bh * 8 + r) * 128 + bw * 8 + c;
        const uint4 hv = *(const uint4*)(g_xph + xbase + (size_t)sp * 256 + q8 * 8);
        const __half2 x0 = *(const __half2*)&hv.x;
        const __half2 x1 = *(const __half2*)&hv.y;
        const __half2 x2 = *(const __half2*)&hv.z;
        const __half2 x3 = *(const __half2*)&hv.w;
        sXT[(q8 * 8 + 0) * HROW + p] = __low2half(x0);
        sXT[(q8 * 8 + 1) * HROW + p] = __high2half(x0);
        sXT[(q8 * 8 + 2) * HROW + p] = __low2half(x1);
        sXT[(q8 * 8 + 3) * HROW + p] = __high2half(x1);
        sXT[(q8 * 8 + 4) * HROW + p] = __low2half(x2);
        sXT[(q8 * 8 + 5) * HROW + p] = __high2half(x2);
        sXT[(q8 * 8 + 6) * HROW + p] = __low2half(x3);
        sXT[(q8 * 8 + 7) * HROW + p] = __high2half(x3);
    }
    // ---- stage X^T: selected 16 tokens, weighted
    {
        const int j    = t >> 3;
        const int dq   = t & 7;
        const int base = (b * 256 + blk) * 16 + j;
        const int tok  = idx[base];
        const float w  = wsel[base];
        const uint2 hv = *(const uint2*)(g_xph + xbase + (size_t)tok * 256 + dq * 4);
        const float2 f0 = __half22float2(*(const __half2*)&hv.x);
        const float2 f1 = __half22float2(*(const __half2*)&hv.y);
        sXT[(dq * 4 + 0) * HROW + 64 + j] = __float2half_rn(f0.x * w);
        sXT[(dq * 4 + 1) * HROW + 64 + j] = __float2half_rn(f0.y * w);
        sXT[(dq * 4 + 2) * HROW + 64 + j] = __float2half_rn(f1.x * w);
        sXT[(dq * 4 + 3) * HROW + 64 + j] = __float2half_rn(f1.y * w);
    }
    __syncthreads();

    const int m0 = warp << 4;
    const uint32_t aoff = sAb  + (uint32_t)(m0 + (lane & 15)) * HROWB +
                          ((lane >> 4) << 4);
    const uint32_t boff = sXTb + (uint32_t)(lane & 15) * HROWB +
                          ((lane >> 4) << 4);

    float acc[4][4];
#pragma unroll
    for (int i = 0; i < 4; i++)
#pragma unroll
        for (int j = 0; j < 4; j++) acc[i][j] = 0.f;

#pragma unroll
    for (int ks = 0; ks < 5; ks++) {
        const uint32_t kb = ks * 32;
        uint32_t ah[4], bf[4][2];
        LDSM4(ah[0], ah[1], ah[2], ah[3], aoff + kb);
#pragma unroll
        for (int np = 0; np < 2; np++) {
            uint32_t r0, r1, r2, r3;
            LDSM4(r0, r1, r2, r3, boff + np * (16 * HROWB) + kb);
            bf[2 * np][0] = r0; bf[2 * np][1] = r2;
            bf[2 * np + 1][0] = r1; bf[2 * np + 1][1] = r3;
        }
#pragma unroll
        for (int nf = 0; nf < 4; nf++)
            mma_fp16(acc[nf], ah, bf[nf]);
    }

    const int g  = lane >> 2;
    const int tg = lane & 3;
#pragma unroll
    for (int nf = 0; nf < 4; nf++) {
#pragma unroll
        for (int half = 0; half < 2; half++) {
            const int q  = m0 + g + half * 8;
            const int r  = q >> 3, c = q & 7;
            const int sp = (bh * 8 + r) * 128 + bw * 8 + c;
            __half2 o = __floats2half2_rn(acc[nf][half * 2 + 0],
                                          acc[nf][half * 2 + 1]);
            *(uint32_t*)(g_yh + xbase + (size_t)sp * 256 + nf * 8 + tg * 2) =
                *(uint32_t*)&o;
        }
    }
}

// ===========================================================================
extern "C" void kernel_launch(void* const* d_in, const int* in_sizes, int n_in,
                              void* d_out, int out_size)
{
    const float* x    = (const float*)d_in[0];
    const float* aw   = (const float*)d_in[1];
    const int*   idx  = (const int*)d_in[2];
    const float* wsel = (const float*)d_in[3];
    const float* Win  = (const float*)d_in[4];
    const float* bin  = (const float*)d_in[5];
    const float* Wout = (const float*)d_in[6];
    const float* bout = (const float*)d_in[7];
    float* out = (float*)d_out;

    __half *xph, *yh, *wt1, *wt2;
    cudaGetSymbolAddress((void**)&xph, g_xph);
    cudaGetSymbolAddress((void**)&yh, g_yh);
    cudaGetSymbolAddress((void**)&wt1, g_wt1);
    cudaGetSymbolAddress((void**)&wt2, g_wt2);

    cudaFuncSetAttribute(gemm_f32in_f16out,
                         cudaFuncAttributeMaxDynamicSharedMemorySize, GEMM1_SMEM);
    cudaFuncSetAttribute(gemm_f16in_f32out,
                         cudaFuncAttributeMaxDynamicSharedMemorySize, GEMM2_SMEM);

    transpose_both<<<128, 256>>>(Win, wt1, Wout, wt2);

    gemm_f32in_f16out<<<dim3(2, 1024), 256, GEMM1_SMEM>>>(x, wt1, bin, xph);
    attn_mma<<<16384, 128>>>(aw, idx, wsel);
    gemm_f16in_f32out<<<dim3(2, 1024), 256, GEMM2_SMEM>>>(yh, wt2, bout, out);
}